// round 9
// baseline (speedup 1.0000x reference)
#include <cuda_runtime.h>
#include <math.h>

#define NCLUST 196
#define CPAD 224             // padded cluster stride (7 warps)
#define DIM 256
#define NROWS 262144
#define TEMP_INV 2.0f        // 1/TEMPERATURE
#define EPSV 1e-12f

// -------- scratch (device globals; no allocation allowed) --------
// column-major segment sums: g_sums[m][d * CPAD + c]
__device__ float g_sums[2][DIM * CPAD];
struct Meta {
    int counts[NCLUST];
    int cursor[NCLUST];
    int done;
    float loss_sum;
};
__device__ Meta g_m;                            // zeroed by one memset
__device__ unsigned g_pack[NROWS];              // (label<<18) | row

// -------- 1. histogram. 64 blocks (minimize contended global atomics) ----
__global__ void k_hist(const int* __restrict__ labels) {
    __shared__ int s_cnt[NCLUST];
    for (int i = threadIdx.x; i < NCLUST; i += blockDim.x) s_cnt[i] = 0;
    __syncthreads();
    const int4* l4 = (const int4*)labels;
    for (int r = blockIdx.x * blockDim.x + threadIdx.x; r < NROWS / 4;
         r += gridDim.x * blockDim.x) {
        int4 v = l4[r];
        atomicAdd(&s_cnt[v.x], 1);
        atomicAdd(&s_cnt[v.y], 1);
        atomicAdd(&s_cnt[v.z], 1);
        atomicAdd(&s_cnt[v.w], 1);
    }
    __syncthreads();
    for (int i = threadIdx.x; i < NCLUST; i += blockDim.x)
        if (s_cnt[i]) atomicAdd(&g_m.counts[i], s_cnt[i]);
}

// -------- 2. scatter (scan fused). 128 blocks x 256, 2048 rows/block ----
__global__ void __launch_bounds__(256) k_scatter(const int* __restrict__ labels) {
    __shared__ int s_hist[NCLUST];
    __shared__ int s_base[NCLUST];
    __shared__ int s_scan[256];
    const int t = threadIdx.x;

    int cv = (t < NCLUST) ? g_m.counts[t] : 0;
    s_scan[t] = cv;
    for (int i = t; i < NCLUST; i += 256) s_hist[i] = 0;
    __syncthreads();
#pragma unroll
    for (int off = 1; off < 256; off <<= 1) {
        int add = (t >= off) ? s_scan[t - off] : 0;
        __syncthreads();
        s_scan[t] += add;
        __syncthreads();
    }

    const int r0 = blockIdx.x * 2048;
    int labs[8], rk[8];
#pragma unroll
    for (int u = 0; u < 8; u++) labs[u] = labels[r0 + u * 256 + t];
#pragma unroll
    for (int u = 0; u < 8; u++) rk[u] = atomicAdd(&s_hist[labs[u]], 1);
    __syncthreads();
    if (t < NCLUST) {
        int h = s_hist[t];
        if (h) s_base[t] = (s_scan[t] - cv) + atomicAdd(&g_m.cursor[t], h);
    }
    __syncthreads();
#pragma unroll
    for (int u = 0; u < 8; u++) {
        int c = labs[u];
        int p = s_base[c] + rk[u];
        g_pack[p] = ((unsigned)c << 18) | (unsigned)(r0 + u * 256 + t);
    }
}

// -------- 3. segment sums over label-sorted rows (hot kernel) --------
// Reads row-major inputs; flushes into COLUMN-MAJOR sums s[d*CPAD + c].
__global__ void __launch_bounds__(256, 5) k_segsum(const float* __restrict__ xq,
                                                   const float* __restrict__ xk) {
    const float* __restrict__ x = blockIdx.y ? xk : xq;
    float* sums = &g_sums[blockIdx.y][0];
    const int t = threadIdx.x;
    const int dq = (t & 63) * 4;      // dim-quad base
    const int sub = t >> 6;           // 0..3
    const int start = blockIdx.x * 256;

    int cur = (int)(g_pack[start + sub] >> 18);
    float4 acc = make_float4(0.f, 0.f, 0.f, 0.f);

    for (int it = 0; it < 64; it += 8) {
        unsigned pk[8];
        float4 v[8];
#pragma unroll
        for (int u = 0; u < 8; u++)
            pk[u] = g_pack[start + sub + (it + u) * 4];
#pragma unroll
        for (int u = 0; u < 8; u++)
            v[u] = __ldcs((const float4*)&x[(size_t)(pk[u] & 0x3FFFFu) * DIM + dq]);
#pragma unroll
        for (int u = 0; u < 8; u++) {
            int lb = (int)(pk[u] >> 18);
            if (lb != cur) {
                atomicAdd(&sums[(dq + 0) * CPAD + cur], acc.x);
                atomicAdd(&sums[(dq + 1) * CPAD + cur], acc.y);
                atomicAdd(&sums[(dq + 2) * CPAD + cur], acc.z);
                atomicAdd(&sums[(dq + 3) * CPAD + cur], acc.w);
                acc = make_float4(0.f, 0.f, 0.f, 0.f);
                cur = lb;
            }
            acc.x += v[u].x;
            acc.y += v[u].y;
            acc.z += v[u].z;
            acc.w += v[u].w;
        }
    }
    atomicAdd(&sums[(dq + 0) * CPAD + cur], acc.x);
    atomicAdd(&sums[(dq + 1) * CPAD + cur], acc.y);
    atomicAdd(&sums[(dq + 2) * CPAD + cur], acc.z);
    atomicAdd(&sums[(dq + 3) * CPAD + cur], acc.w);
}

// -------- 4. loss on RAW column-major sums, no hot-loop reductions ------
// grid 98 x 224 thr. Thread j owns matrix column j; d-loop accumulates
// dot(s_j, s_i0), dot(s_j, s_i1), ||s_j||^2 with q_i[d] smem broadcasts.
__global__ void __launch_bounds__(224) k_loss(float* out) {
    const int i0 = blockIdx.x * 2;
    const int i1 = i0 + 1;
    const int tid = threadIdx.x;
    const int lane = tid & 31, w = tid >> 5;
    __shared__ float s_q0[DIM], s_q1[DIM], s_k0[DIM], s_k1[DIM];
    __shared__ float s_n[CPAD];
    __shared__ float s_row0[NCLUST], s_row1[NCLUST];
    __shared__ float s_dkraw[2], s_nk[2];
    __shared__ float s_r0[7], s_r1[7];
    __shared__ float s_mx0, s_mx1, s_sum0, s_sum1;

    const float* sq = &g_sums[0][0];
    const float* sk = &g_sums[1][0];

    // gather the two i-rows (strided; one load per thread-ish)
    for (int d = tid; d < DIM; d += 224) {
        s_q0[d] = sq[d * CPAD + i0];
        s_q1[d] = sq[d * CPAD + i1];
        s_k0[d] = sk[d * CPAD + i0];
        s_k1[d] = sk[d * CPAD + i1];
    }
    __syncthreads();

    // main loop: coalesced column loads, zero shuffles
    float p0 = 0.f, p1 = 0.f, nn = 0.f;
#pragma unroll 8
    for (int d = 0; d < DIM; d++) {
        float sv = sq[d * CPAD + tid];
        p0 = fmaf(sv, s_q0[d], p0);
        p1 = fmaf(sv, s_q1[d], p1);
        nn = fmaf(sv, sv, nn);
    }
    s_n[tid] = nn;

    // k-diagonals from smem (2 warps)
    if (w < 2) {
        const float* qq = w ? s_q1 : s_q0;
        const float* kk = w ? s_k1 : s_k0;
        float p = 0.f, n2 = 0.f;
#pragma unroll
        for (int m = 0; m < 8; m++) {
            float kv = kk[m * 32 + lane];
            p = fmaf(qq[m * 32 + lane], kv, p);
            n2 = fmaf(kv, kv, n2);
        }
#pragma unroll
        for (int off = 16; off > 0; off >>= 1) {
            p += __shfl_xor_sync(0xFFFFFFFFu, p, off);
            n2 += __shfl_xor_sync(0xFFFFFFFFu, n2, off);
        }
        if (lane == 0) { s_dkraw[w] = p; s_nk[w] = n2; }
    }
    __syncthreads();

    // scale + mask per thread j
    const float inv0 = 1.0f / fmaxf(sqrtf(s_n[i0]), EPSV);
    const float inv1 = 1.0f / fmaxf(sqrtf(s_n[i1]), EPSV);
    float r0 = -1e30f, r1 = -1e30f;
    if (tid < NCLUST) {
        float invj = 1.0f / fmaxf(sqrtf(s_n[tid]), EPSV);
        if (tid == i0)
            r0 = s_dkraw[0] * inv0 / fmaxf(sqrtf(s_nk[0]), EPSV) * TEMP_INV;
        else
            r0 = p0 * inv0 * invj * TEMP_INV;
        if (tid == i1)
            r1 = s_dkraw[1] * inv1 / fmaxf(sqrtf(s_nk[1]), EPSV) * TEMP_INV;
        else
            r1 = p1 * inv1 * invj * TEMP_INV;
        if (g_m.counts[tid] == 0) { r0 = -10.0f; r1 = -10.0f; }
        s_row0[tid] = r0;
        s_row1[tid] = r1;
    }
    __syncthreads();

    // max reduce (7 warps)
    float v0 = r0, v1 = r1;
#pragma unroll
    for (int off = 16; off > 0; off >>= 1) {
        v0 = fmaxf(v0, __shfl_xor_sync(0xFFFFFFFFu, v0, off));
        v1 = fmaxf(v1, __shfl_xor_sync(0xFFFFFFFFu, v1, off));
    }
    if (lane == 0) { s_r0[w] = v0; s_r1[w] = v1; }
    __syncthreads();
    if (tid == 0) {
        float m0 = s_r0[0], m1 = s_r1[0];
        for (int k = 1; k < 7; k++) {
            m0 = fmaxf(m0, s_r0[k]);
            m1 = fmaxf(m1, s_r1[k]);
        }
        s_mx0 = m0; s_mx1 = m1;
    }
    __syncthreads();
    float mx0 = s_mx0, mx1 = s_mx1;

    float e0 = (tid < NCLUST) ? __expf(s_row0[tid] - mx0) : 0.0f;
    float e1 = (tid < NCLUST) ? __expf(s_row1[tid] - mx1) : 0.0f;
#pragma unroll
    for (int off = 16; off > 0; off >>= 1) {
        e0 += __shfl_xor_sync(0xFFFFFFFFu, e0, off);
        e1 += __shfl_xor_sync(0xFFFFFFFFu, e1, off);
    }
    if (lane == 0) { s_r0[w] = e0; s_r1[w] = e1; }
    __syncthreads();
    if (tid == 0) {
        float t0 = 0.f, t1 = 0.f;
        for (int k = 0; k < 7; k++) { t0 += s_r0[k]; t1 += s_r1[k]; }
        s_sum0 = t0; s_sum1 = t1;
    }
    __syncthreads();

    if (tid == 0) {
        float loss = 0.0f;
        if (g_m.counts[i0] != 0) loss += -s_row0[i0] + mx0 + logf(s_sum0);
        if (g_m.counts[i1] != 0) loss += -s_row1[i1] + mx1 + logf(s_sum1);
        if (loss != 0.0f) atomicAdd(&g_m.loss_sum, loss);
        __threadfence();
        int ticket = atomicAdd(&g_m.done, 1);
        if (ticket == NCLUST / 2 - 1) {
            float tot = atomicAdd(&g_m.loss_sum, 0.0f);
            int nz = 0;
            for (int k = 0; k < NCLUST; k++)
                if (g_m.counts[k] == 0) nz++;
            out[0] = tot / ((float)NCLUST - (float)nz);
        }
    }
}

extern "C" void kernel_launch(void* const* d_in, const int* in_sizes, int n_in,
                              void* d_out, int out_size) {
    const float* im_q = (const float*)d_in[0];
    const float* im_k = (const float*)d_in[1];
    const int* labels = (const int*)d_in[2];
    float* out = (float*)d_out;

    void *p_sums = 0, *p_meta = 0;
    cudaGetSymbolAddress(&p_sums, g_sums);
    cudaGetSymbolAddress(&p_meta, g_m);
    cudaMemsetAsync(p_sums, 0, sizeof(float) * 2 * DIM * CPAD);
    cudaMemsetAsync(p_meta, 0, sizeof(Meta));

    k_hist<<<64, 256>>>(labels);
    k_scatter<<<128, 256>>>(labels);
    dim3 gs(NROWS / 256, 2);
    k_segsum<<<gs, 256>>>(im_q, im_k);
    k_loss<<<NCLUST / 2, 224>>>(out);
}

// round 10
// speedup vs baseline: 1.1302x; 1.1302x over previous
#include <cuda_runtime.h>
#include <math.h>

#define NCLUST 196
#define DIM 256
#define NROWS 262144
#define TEMP_INV 2.0f        // 1/TEMPERATURE
#define EPSV 1e-12f

// -------- scratch (device globals; no allocation allowed) --------
__device__ float g_sums[2][NCLUST * DIM];       // [q,k] raw segment sums
struct Meta {
    int counts[NCLUST];
    int cursor[NCLUST];
    int done;
    float loss_sum;
};
__device__ Meta g_m;                            // zeroed by one memset
__device__ unsigned g_pack[NROWS];              // (label<<18) | row

// -------- 1. histogram. 64 blocks (minimize contended global atomics) ----
__global__ void k_hist(const int* __restrict__ labels) {
    __shared__ int s_cnt[NCLUST];
    for (int i = threadIdx.x; i < NCLUST; i += blockDim.x) s_cnt[i] = 0;
    __syncthreads();
    const int4* l4 = (const int4*)labels;
    for (int r = blockIdx.x * blockDim.x + threadIdx.x; r < NROWS / 4;
         r += gridDim.x * blockDim.x) {
        int4 v = l4[r];
        atomicAdd(&s_cnt[v.x], 1);
        atomicAdd(&s_cnt[v.y], 1);
        atomicAdd(&s_cnt[v.z], 1);
        atomicAdd(&s_cnt[v.w], 1);
    }
    __syncthreads();
    for (int i = threadIdx.x; i < NCLUST; i += blockDim.x)
        if (s_cnt[i]) atomicAdd(&g_m.counts[i], s_cnt[i]);
}

// -------- 2. scatter (scan fused). 128 blocks x 256, 2048 rows/block ----
__global__ void __launch_bounds__(256) k_scatter(const int* __restrict__ labels) {
    __shared__ int s_hist[NCLUST];
    __shared__ int s_base[NCLUST];
    __shared__ int s_scan[256];
    const int t = threadIdx.x;

    int cv = (t < NCLUST) ? g_m.counts[t] : 0;
    s_scan[t] = cv;
    for (int i = t; i < NCLUST; i += 256) s_hist[i] = 0;
    __syncthreads();
#pragma unroll
    for (int off = 1; off < 256; off <<= 1) {
        int add = (t >= off) ? s_scan[t - off] : 0;
        __syncthreads();
        s_scan[t] += add;
        __syncthreads();
    }

    const int r0 = blockIdx.x * 2048;
    int labs[8], rk[8];
#pragma unroll
    for (int u = 0; u < 8; u++) labs[u] = labels[r0 + u * 256 + t];
#pragma unroll
    for (int u = 0; u < 8; u++) rk[u] = atomicAdd(&s_hist[labs[u]], 1);
    __syncthreads();
    if (t < NCLUST) {
        int h = s_hist[t];
        if (h) s_base[t] = (s_scan[t] - cv) + atomicAdd(&g_m.cursor[t], h);
    }
    __syncthreads();
#pragma unroll
    for (int u = 0; u < 8; u++) {
        int c = labs[u];
        int p = s_base[c] + rk[u];
        g_pack[p] = ((unsigned)c << 18) | (unsigned)(r0 + u * 256 + t);
    }
}

// -------- 3. segment sums over label-sorted rows (hot kernel, R8) --------
__global__ void __launch_bounds__(256, 5) k_segsum(const float* __restrict__ xq,
                                                   const float* __restrict__ xk) {
    const float* __restrict__ x = blockIdx.y ? xk : xq;
    float* sums = &g_sums[blockIdx.y][0];
    const int t = threadIdx.x;
    const int dq = (t & 63) * 4;      // dim-quad base
    const int sub = t >> 6;           // 0..3
    const int start = blockIdx.x * 256;

    int cur = (int)(g_pack[start + sub] >> 18);
    float4 acc = make_float4(0.f, 0.f, 0.f, 0.f);

    for (int it = 0; it < 64; it += 8) {
        unsigned pk[8];
        float4 v[8];
#pragma unroll
        for (int u = 0; u < 8; u++)
            pk[u] = g_pack[start + sub + (it + u) * 4];
#pragma unroll
        for (int u = 0; u < 8; u++)
            v[u] = __ldcs((const float4*)&x[(size_t)(pk[u] & 0x3FFFFu) * DIM + dq]);
#pragma unroll
        for (int u = 0; u < 8; u++) {
            int lb = (int)(pk[u] >> 18);
            if (lb != cur) {
                float* dst = &sums[cur * DIM + dq];
                atomicAdd(dst + 0, acc.x);
                atomicAdd(dst + 1, acc.y);
                atomicAdd(dst + 2, acc.z);
                atomicAdd(dst + 3, acc.w);
                acc = make_float4(0.f, 0.f, 0.f, 0.f);
                cur = lb;
            }
            acc.x += v[u].x;
            acc.y += v[u].y;
            acc.z += v[u].z;
            acc.w += v[u].w;
        }
    }
    float* dst = &sums[cur * DIM + dq];
    atomicAdd(dst + 0, acc.x);
    atomicAdd(dst + 1, acc.y);
    atomicAdd(dst + 2, acc.z);
    atomicAdd(dst + 3, acc.w);
}

// -------- 4. loss on RAW sums, 512 thr, 4-j rounds for ILP --------------
// dot(c_i,c_j) = dot(s_i,s_j)*inv_i*inv_j. 2 i-rows per block, grid 98.
// Warp w owns j in {w, w+16, ...}; rounds process 4 j's concurrently so
// the 12 shfl-reduction trees interleave instead of serializing.
__global__ void __launch_bounds__(512) k_loss(float* out) {
    const int i0 = blockIdx.x * 2;
    const int i1 = i0 + 1;
    const int tid = threadIdx.x;
    const int lane = tid & 31, w = tid >> 5;
    __shared__ float s_q0[DIM], s_q1[DIM];
    __shared__ float s_row0[NCLUST], s_row1[NCLUST];
    __shared__ float s_n[NCLUST];
    __shared__ float s_dkraw[2], s_nk[2];
    __shared__ float s_r0[16], s_r1[16];
    __shared__ float s_mx0, s_mx1, s_sum0, s_sum1;

    const float* sq = &g_sums[0][0];
    const float* sk = &g_sums[1][0];

    if (tid < DIM) {
        s_q0[tid] = sq[i0 * DIM + tid];
        s_q1[tid] = sq[i1 * DIM + tid];
    }
    __syncthreads();

    const float4* q0v = (const float4*)s_q0;
    const float4* q1v = (const float4*)s_q1;
    const float4 a0 = q0v[lane], b0 = q0v[32 + lane];
    const float4 a1 = q1v[lane], b1 = q1v[32 + lane];

    // rounds r=0..2: 4 j's each (j = w + r*64 + g*16, all < 196).
    // tail: j = w + 192 for w < 4.
#pragma unroll
    for (int r = 0; r < 3; r++) {
        float4 va[4], vb[4];
        float p0[4], p1[4], nn[4];
#pragma unroll
        for (int g = 0; g < 4; g++) {
            const float4* vj = (const float4*)&sq[(w + r * 64 + g * 16) * DIM];
            va[g] = vj[lane];
            vb[g] = vj[32 + lane];
        }
#pragma unroll
        for (int g = 0; g < 4; g++) {
            p0[g] = va[g].x * a0.x + va[g].y * a0.y + va[g].z * a0.z + va[g].w * a0.w
                  + vb[g].x * b0.x + vb[g].y * b0.y + vb[g].z * b0.z + vb[g].w * b0.w;
            p1[g] = va[g].x * a1.x + va[g].y * a1.y + va[g].z * a1.z + va[g].w * a1.w
                  + vb[g].x * b1.x + vb[g].y * b1.y + vb[g].z * b1.z + vb[g].w * b1.w;
            nn[g] = va[g].x * va[g].x + va[g].y * va[g].y + va[g].z * va[g].z + va[g].w * va[g].w
                  + vb[g].x * vb[g].x + vb[g].y * vb[g].y + vb[g].z * vb[g].z + vb[g].w * vb[g].w;
        }
#pragma unroll
        for (int off = 16; off > 0; off >>= 1) {
#pragma unroll
            for (int g = 0; g < 4; g++) {
                p0[g] += __shfl_xor_sync(0xFFFFFFFFu, p0[g], off);
                p1[g] += __shfl_xor_sync(0xFFFFFFFFu, p1[g], off);
                nn[g] += __shfl_xor_sync(0xFFFFFFFFu, nn[g], off);
            }
        }
        if (lane == 0) {
#pragma unroll
            for (int g = 0; g < 4; g++) {
                int j = w + r * 64 + g * 16;
                s_row0[j] = p0[g];
                s_row1[j] = p1[g];
                s_n[j] = nn[g];
            }
        }
    }
    if (w < 4) {
        const int j = w + 192;
        const float4* vj = (const float4*)&sq[j * DIM];
        float4 va = vj[lane], vb = vj[32 + lane];
        float p0 = va.x * a0.x + va.y * a0.y + va.z * a0.z + va.w * a0.w
                 + vb.x * b0.x + vb.y * b0.y + vb.z * b0.z + vb.w * b0.w;
        float p1 = va.x * a1.x + va.y * a1.y + va.z * a1.z + va.w * a1.w
                 + vb.x * b1.x + vb.y * b1.y + vb.z * b1.z + vb.w * b1.w;
        float nn = va.x * va.x + va.y * va.y + va.z * va.z + va.w * va.w
                 + vb.x * vb.x + vb.y * vb.y + vb.z * vb.z + vb.w * vb.w;
#pragma unroll
        for (int off = 16; off > 0; off >>= 1) {
            p0 += __shfl_xor_sync(0xFFFFFFFFu, p0, off);
            p1 += __shfl_xor_sync(0xFFFFFFFFu, p1, off);
            nn += __shfl_xor_sync(0xFFFFFFFFu, nn, off);
        }
        if (lane == 0) { s_row0[j] = p0; s_row1[j] = p1; s_n[j] = nn; }
    }
    // k-diagonals (warps 4,5)
    if (w == 4 || w == 5) {
        const int sel = w - 4;
        const float4* vj = (const float4*)&sk[(sel ? i1 : i0) * DIM];
        float4 va = vj[lane], vb = vj[32 + lane];
        float4 ca = sel ? a1 : a0, cb = sel ? b1 : b0;
        float p = va.x * ca.x + va.y * ca.y + va.z * ca.z + va.w * ca.w
                + vb.x * cb.x + vb.y * cb.y + vb.z * cb.z + vb.w * cb.w;
        float nn = va.x * va.x + va.y * va.y + va.z * va.z + va.w * va.w
                 + vb.x * vb.x + vb.y * vb.y + vb.z * vb.z + vb.w * vb.w;
#pragma unroll
        for (int off = 16; off > 0; off >>= 1) {
            p += __shfl_xor_sync(0xFFFFFFFFu, p, off);
            nn += __shfl_xor_sync(0xFFFFFFFFu, nn, off);
        }
        if (lane == 0) { s_dkraw[sel] = p; s_nk[sel] = nn; }
    }
    __syncthreads();

    // scale + mask
    const float inv0 = 1.0f / fmaxf(sqrtf(s_n[i0]), EPSV);
    const float inv1 = 1.0f / fmaxf(sqrtf(s_n[i1]), EPSV);
    float r0 = -1e30f, r1 = -1e30f;
    if (tid < NCLUST) {
        float invj = 1.0f / fmaxf(sqrtf(s_n[tid]), EPSV);
        if (tid == i0)
            r0 = s_dkraw[0] * inv0 / fmaxf(sqrtf(s_nk[0]), EPSV) * TEMP_INV;
        else
            r0 = s_row0[tid] * inv0 * invj * TEMP_INV;
        if (tid == i1)
            r1 = s_dkraw[1] * inv1 / fmaxf(sqrtf(s_nk[1]), EPSV) * TEMP_INV;
        else
            r1 = s_row1[tid] * inv1 * invj * TEMP_INV;
        if (g_m.counts[tid] == 0) { r0 = -10.0f; r1 = -10.0f; }
        s_row0[tid] = r0;
        s_row1[tid] = r1;
    }
    __syncthreads();

    float v0 = r0, v1 = r1;
#pragma unroll
    for (int off = 16; off > 0; off >>= 1) {
        v0 = fmaxf(v0, __shfl_xor_sync(0xFFFFFFFFu, v0, off));
        v1 = fmaxf(v1, __shfl_xor_sync(0xFFFFFFFFu, v1, off));
    }
    if (lane == 0) { s_r0[w] = v0; s_r1[w] = v1; }
    __syncthreads();
    if (tid == 0) {
        float m0 = s_r0[0], m1 = s_r1[0];
        for (int k = 1; k < 16; k++) {
            m0 = fmaxf(m0, s_r0[k]);
            m1 = fmaxf(m1, s_r1[k]);
        }
        s_mx0 = m0; s_mx1 = m1;
    }
    __syncthreads();
    float mx0 = s_mx0, mx1 = s_mx1;

    float e0 = (tid < NCLUST) ? __expf(s_row0[tid] - mx0) : 0.0f;
    float e1 = (tid < NCLUST) ? __expf(s_row1[tid] - mx1) : 0.0f;
#pragma unroll
    for (int off = 16; off > 0; off >>= 1) {
        e0 += __shfl_xor_sync(0xFFFFFFFFu, e0, off);
        e1 += __shfl_xor_sync(0xFFFFFFFFu, e1, off);
    }
    if (lane == 0) { s_r0[w] = e0; s_r1[w] = e1; }
    __syncthreads();
    if (tid == 0) {
        float t0 = 0.f, t1 = 0.f;
        for (int k = 0; k < 16; k++) { t0 += s_r0[k]; t1 += s_r1[k]; }
        s_sum0 = t0; s_sum1 = t1;
    }
    __syncthreads();

    if (tid == 0) {
        float loss = 0.0f;
        if (g_m.counts[i0] != 0) loss += -s_row0[i0] + mx0 + logf(s_sum0);
        if (g_m.counts[i1] != 0) loss += -s_row1[i1] + mx1 + logf(s_sum1);
        if (loss != 0.0f) atomicAdd(&g_m.loss_sum, loss);
        __threadfence();
        int ticket = atomicAdd(&g_m.done, 1);
        if (ticket == NCLUST / 2 - 1) {
            float tot = atomicAdd(&g_m.loss_sum, 0.0f);
            int nz = 0;
            for (int k = 0; k < NCLUST; k++)
                if (g_m.counts[k] == 0) nz++;
            out[0] = tot / ((float)NCLUST - (float)nz);
        }
    }
}

extern "C" void kernel_launch(void* const* d_in, const int* in_sizes, int n_in,
                              void* d_out, int out_size) {
    const float* im_q = (const float*)d_in[0];
    const float* im_k = (const float*)d_in[1];
    const int* labels = (const int*)d_in[2];
    float* out = (float*)d_out;

    void *p_sums = 0, *p_meta = 0;
    cudaGetSymbolAddress(&p_sums, g_sums);
    cudaGetSymbolAddress(&p_meta, g_m);
    cudaMemsetAsync(p_sums, 0, sizeof(float) * 2 * NCLUST * DIM);
    cudaMemsetAsync(p_meta, 0, sizeof(Meta));

    k_hist<<<64, 256>>>(labels);
    k_scatter<<<128, 256>>>(labels);
    dim3 gs(NROWS / 256, 2);
    k_segsum<<<gs, 256>>>(im_q, im_k);
    k_loss<<<NCLUST / 2, 512>>>(out);
}

// round 11
// speedup vs baseline: 1.1482x; 1.0159x over previous
#include <cuda_runtime.h>
#include <math.h>

#define NCLUST 196
#define DIM 256
#define NROWS 262144
#define TEMP_INV 2.0f        // 1/TEMPERATURE
#define EPSV 1e-12f

// -------- scratch (device globals; no allocation allowed) --------
__device__ float g_sums[2][NCLUST * DIM];       // [q,k] raw segment sums
struct Meta {
    int counts[NCLUST];
    int cursor[NCLUST];
    int done;
    int nzero;
    float loss_sum;
};
__device__ Meta g_m;                            // zeroed by one memset
__device__ unsigned g_pack[NROWS];              // (label<<18) | row

// -------- 1. histogram. 64 blocks (minimize contended global atomics) ----
__global__ void k_hist(const int* __restrict__ labels) {
    __shared__ int s_cnt[NCLUST];
    for (int i = threadIdx.x; i < NCLUST; i += blockDim.x) s_cnt[i] = 0;
    __syncthreads();
    const int4* l4 = (const int4*)labels;
    for (int r = blockIdx.x * blockDim.x + threadIdx.x; r < NROWS / 4;
         r += gridDim.x * blockDim.x) {
        int4 v = l4[r];
        atomicAdd(&s_cnt[v.x], 1);
        atomicAdd(&s_cnt[v.y], 1);
        atomicAdd(&s_cnt[v.z], 1);
        atomicAdd(&s_cnt[v.w], 1);
    }
    __syncthreads();
    for (int i = threadIdx.x; i < NCLUST; i += blockDim.x)
        if (s_cnt[i]) atomicAdd(&g_m.counts[i], s_cnt[i]);
}

// -------- 2. scatter (scan fused). 128 blocks x 256, 2048 rows/block ----
__global__ void __launch_bounds__(256) k_scatter(const int* __restrict__ labels) {
    __shared__ int s_hist[NCLUST];
    __shared__ int s_base[NCLUST];
    __shared__ int s_scan[256];
    const int t = threadIdx.x;

    int cv = (t < NCLUST) ? g_m.counts[t] : 0;
    s_scan[t] = cv;
    for (int i = t; i < NCLUST; i += 256) s_hist[i] = 0;
    // block 0 precomputes n_zero for k_loss's final mean
    if (blockIdx.x == 0 && t < NCLUST && cv == 0) atomicAdd(&g_m.nzero, 1);
    __syncthreads();
#pragma unroll
    for (int off = 1; off < 256; off <<= 1) {
        int add = (t >= off) ? s_scan[t - off] : 0;
        __syncthreads();
        s_scan[t] += add;
        __syncthreads();
    }

    const int r0 = blockIdx.x * 2048;
    int labs[8], rk[8];
#pragma unroll
    for (int u = 0; u < 8; u++) labs[u] = labels[r0 + u * 256 + t];
#pragma unroll
    for (int u = 0; u < 8; u++) rk[u] = atomicAdd(&s_hist[labs[u]], 1);
    __syncthreads();
    if (t < NCLUST) {
        int h = s_hist[t];
        if (h) s_base[t] = (s_scan[t] - cv) + atomicAdd(&g_m.cursor[t], h);
    }
    __syncthreads();
#pragma unroll
    for (int u = 0; u < 8; u++) {
        int c = labs[u];
        int p = s_base[c] + rk[u];
        g_pack[p] = ((unsigned)c << 18) | (unsigned)(r0 + u * 256 + t);
    }
}

// -------- 3. segment sums over label-sorted rows (hot kernel, R8) --------
__global__ void __launch_bounds__(256, 5) k_segsum(const float* __restrict__ xq,
                                                   const float* __restrict__ xk) {
    const float* __restrict__ x = blockIdx.y ? xk : xq;
    float* sums = &g_sums[blockIdx.y][0];
    const int t = threadIdx.x;
    const int dq = (t & 63) * 4;      // dim-quad base
    const int sub = t >> 6;           // 0..3
    const int start = blockIdx.x * 256;

    int cur = (int)(g_pack[start + sub] >> 18);
    float4 acc = make_float4(0.f, 0.f, 0.f, 0.f);

    for (int it = 0; it < 64; it += 8) {
        unsigned pk[8];
        float4 v[8];
#pragma unroll
        for (int u = 0; u < 8; u++)
            pk[u] = g_pack[start + sub + (it + u) * 4];
#pragma unroll
        for (int u = 0; u < 8; u++)
            v[u] = __ldcs((const float4*)&x[(size_t)(pk[u] & 0x3FFFFu) * DIM + dq]);
#pragma unroll
        for (int u = 0; u < 8; u++) {
            int lb = (int)(pk[u] >> 18);
            if (lb != cur) {
                float* dst = &sums[cur * DIM + dq];
                atomicAdd(dst + 0, acc.x);
                atomicAdd(dst + 1, acc.y);
                atomicAdd(dst + 2, acc.z);
                atomicAdd(dst + 3, acc.w);
                acc = make_float4(0.f, 0.f, 0.f, 0.f);
                cur = lb;
            }
            acc.x += v[u].x;
            acc.y += v[u].y;
            acc.z += v[u].z;
            acc.w += v[u].w;
        }
    }
    float* dst = &sums[cur * DIM + dq];
    atomicAdd(dst + 0, acc.x);
    atomicAdd(dst + 1, acc.y);
    atomicAdd(dst + 2, acc.z);
    atomicAdd(dst + 3, acc.w);
}

// -------- 4. loss on RAW sums, 1024 thr, two 3-j rounds + tail ----------
// dot(c_i,c_j) = dot(s_i,s_j)*inv_i*inv_j. 2 i-rows per block, grid 98.
// 32 warps: warp w owns j in {w, w+32, ...}; 9 shfl trees interleave/round.
__global__ void __launch_bounds__(1024) k_loss(float* out) {
    const int i0 = blockIdx.x * 2;
    const int i1 = i0 + 1;
    const int tid = threadIdx.x;
    const int lane = tid & 31, w = tid >> 5;
    __shared__ float s_q0[DIM], s_q1[DIM];
    __shared__ float s_row0[NCLUST], s_row1[NCLUST];
    __shared__ float s_n[NCLUST];
    __shared__ float s_dkraw[2], s_nk[2];
    __shared__ float s_r0[32], s_r1[32];
    __shared__ float s_mx0, s_mx1, s_sum0, s_sum1;

    const float* sq = &g_sums[0][0];
    const float* sk = &g_sums[1][0];

    if (tid < DIM) {
        s_q0[tid] = sq[i0 * DIM + tid];
        s_q1[tid] = sq[i1 * DIM + tid];
    }
    __syncthreads();

    const float4* q0v = (const float4*)s_q0;
    const float4* q1v = (const float4*)s_q1;
    const float4 a0 = q0v[lane], b0 = q0v[32 + lane];
    const float4 a1 = q1v[lane], b1 = q1v[32 + lane];

    // rounds r=0,1: j = w + (r*3+g)*32, g=0..2 (all < 192).
#pragma unroll
    for (int r = 0; r < 2; r++) {
        float4 va[3], vb[3];
        float p0[3], p1[3], nn[3];
#pragma unroll
        for (int g = 0; g < 3; g++) {
            const float4* vj = (const float4*)&sq[(w + (r * 3 + g) * 32) * DIM];
            va[g] = vj[lane];
            vb[g] = vj[32 + lane];
        }
#pragma unroll
        for (int g = 0; g < 3; g++) {
            p0[g] = va[g].x * a0.x + va[g].y * a0.y + va[g].z * a0.z + va[g].w * a0.w
                  + vb[g].x * b0.x + vb[g].y * b0.y + vb[g].z * b0.z + vb[g].w * b0.w;
            p1[g] = va[g].x * a1.x + va[g].y * a1.y + va[g].z * a1.z + va[g].w * a1.w
                  + vb[g].x * b1.x + vb[g].y * b1.y + vb[g].z * b1.z + vb[g].w * b1.w;
            nn[g] = va[g].x * va[g].x + va[g].y * va[g].y + va[g].z * va[g].z + va[g].w * va[g].w
                  + vb[g].x * vb[g].x + vb[g].y * vb[g].y + vb[g].z * vb[g].z + vb[g].w * vb[g].w;
        }
#pragma unroll
        for (int off = 16; off > 0; off >>= 1) {
#pragma unroll
            for (int g = 0; g < 3; g++) {
                p0[g] += __shfl_xor_sync(0xFFFFFFFFu, p0[g], off);
                p1[g] += __shfl_xor_sync(0xFFFFFFFFu, p1[g], off);
                nn[g] += __shfl_xor_sync(0xFFFFFFFFu, nn[g], off);
            }
        }
        if (lane == 0) {
#pragma unroll
            for (int g = 0; g < 3; g++) {
                int j = w + (r * 3 + g) * 32;
                s_row0[j] = p0[g];
                s_row1[j] = p1[g];
                s_n[j] = nn[g];
            }
        }
    }
    // tail: j = 192 + w for w < 4
    if (w < 4) {
        const int j = w + 192;
        const float4* vj = (const float4*)&sq[j * DIM];
        float4 va = vj[lane], vb = vj[32 + lane];
        float p0 = va.x * a0.x + va.y * a0.y + va.z * a0.z + va.w * a0.w
                 + vb.x * b0.x + vb.y * b0.y + vb.z * b0.z + vb.w * b0.w;
        float p1 = va.x * a1.x + va.y * a1.y + va.z * a1.z + va.w * a1.w
                 + vb.x * b1.x + vb.y * b1.y + vb.z * b1.z + vb.w * b1.w;
        float nn = va.x * va.x + va.y * va.y + va.z * va.z + va.w * va.w
                 + vb.x * vb.x + vb.y * vb.y + vb.z * vb.z + vb.w * vb.w;
#pragma unroll
        for (int off = 16; off > 0; off >>= 1) {
            p0 += __shfl_xor_sync(0xFFFFFFFFu, p0, off);
            p1 += __shfl_xor_sync(0xFFFFFFFFu, p1, off);
            nn += __shfl_xor_sync(0xFFFFFFFFu, nn, off);
        }
        if (lane == 0) { s_row0[j] = p0; s_row1[j] = p1; s_n[j] = nn; }
    }
    // k-diagonals (warps 4,5)
    if (w == 4 || w == 5) {
        const int sel = w - 4;
        const float4* vj = (const float4*)&sk[(sel ? i1 : i0) * DIM];
        float4 va = vj[lane], vb = vj[32 + lane];
        float4 ca = sel ? a1 : a0, cb = sel ? b1 : b0;
        float p = va.x * ca.x + va.y * ca.y + va.z * ca.z + va.w * ca.w
                + vb.x * cb.x + vb.y * cb.y + vb.z * cb.z + vb.w * cb.w;
        float nn = va.x * va.x + va.y * va.y + va.z * va.z + va.w * va.w
                 + vb.x * vb.x + vb.y * vb.y + vb.z * vb.z + vb.w * vb.w;
#pragma unroll
        for (int off = 16; off > 0; off >>= 1) {
            p += __shfl_xor_sync(0xFFFFFFFFu, p, off);
            nn += __shfl_xor_sync(0xFFFFFFFFu, nn, off);
        }
        if (lane == 0) { s_dkraw[sel] = p; s_nk[sel] = nn; }
    }
    __syncthreads();

    // scale + mask
    const float inv0 = 1.0f / fmaxf(sqrtf(s_n[i0]), EPSV);
    const float inv1 = 1.0f / fmaxf(sqrtf(s_n[i1]), EPSV);
    float r0 = -1e30f, r1 = -1e30f;
    if (tid < NCLUST) {
        float invj = 1.0f / fmaxf(sqrtf(s_n[tid]), EPSV);
        if (tid == i0)
            r0 = s_dkraw[0] * inv0 / fmaxf(sqrtf(s_nk[0]), EPSV) * TEMP_INV;
        else
            r0 = s_row0[tid] * inv0 * invj * TEMP_INV;
        if (tid == i1)
            r1 = s_dkraw[1] * inv1 / fmaxf(sqrtf(s_nk[1]), EPSV) * TEMP_INV;
        else
            r1 = s_row1[tid] * inv1 * invj * TEMP_INV;
        if (g_m.counts[tid] == 0) { r0 = -10.0f; r1 = -10.0f; }
        s_row0[tid] = r0;
        s_row1[tid] = r1;
    }
    __syncthreads();

    float v0 = r0, v1 = r1;
#pragma unroll
    for (int off = 16; off > 0; off >>= 1) {
        v0 = fmaxf(v0, __shfl_xor_sync(0xFFFFFFFFu, v0, off));
        v1 = fmaxf(v1, __shfl_xor_sync(0xFFFFFFFFu, v1, off));
    }
    if (lane == 0) { s_r0[w] = v0; s_r1[w] = v1; }
    __syncthreads();
    if (tid == 0) {
        float m0 = s_r0[0], m1 = s_r1[0];
        for (int k = 1; k < 32; k++) {
            m0 = fmaxf(m0, s_r0[k]);
            m1 = fmaxf(m1, s_r1[k]);
        }
        s_mx0 = m0; s_mx1 = m1;
    }
    __syncthreads();
    float mx0 = s_mx0, mx1 = s_mx1;

    float e0 = (tid < NCLUST) ? __expf(s_row0[tid] - mx0) : 0.0f;
    float e1 = (tid < NCLUST) ? __expf(s_row1[tid] - mx1) : 0.0f;
#pragma unroll
    for (int off = 16; off > 0; off >>= 1) {
        e0 += __shfl_xor_sync(0xFFFFFFFFu, e0, off);
        e1 += __shfl_xor_sync(0xFFFFFFFFu, e1, off);
    }
    if (lane == 0) { s_r0[w] = e0; s_r1[w] = e1; }
    __syncthreads();
    if (tid == 0) {
        float t0 = 0.f, t1 = 0.f;
        for (int k = 0; k < 32; k++) { t0 += s_r0[k]; t1 += s_r1[k]; }
        s_sum0 = t0; s_sum1 = t1;
    }
    __syncthreads();

    if (tid == 0) {
        float loss = 0.0f;
        if (g_m.counts[i0] != 0) loss += -s_row0[i0] + mx0 + logf(s_sum0);
        if (g_m.counts[i1] != 0) loss += -s_row1[i1] + mx1 + logf(s_sum1);
        if (loss != 0.0f) atomicAdd(&g_m.loss_sum, loss);
        __threadfence();
        int ticket = atomicAdd(&g_m.done, 1);
        if (ticket == NCLUST / 2 - 1) {
            float tot = atomicAdd(&g_m.loss_sum, 0.0f);
            out[0] = tot / ((float)NCLUST - (float)g_m.nzero);
        }
    }
}

extern "C" void kernel_launch(void* const* d_in, const int* in_sizes, int n_in,
                              void* d_out, int out_size) {
    const float* im_q = (const float*)d_in[0];
    const float* im_k = (const float*)d_in[1];
    const int* labels = (const int*)d_in[2];
    float* out = (float*)d_out;

    void *p_sums = 0, *p_meta = 0;
    cudaGetSymbolAddress(&p_sums, g_sums);
    cudaGetSymbolAddress(&p_meta, g_m);
    cudaMemsetAsync(p_sums, 0, sizeof(float) * 2 * NCLUST * DIM);
    cudaMemsetAsync(p_meta, 0, sizeof(Meta));

    k_hist<<<64, 256>>>(labels);
    k_scatter<<<128, 256>>>(labels);
    dim3 gs(NROWS / 256, 2);
    k_segsum<<<gs, 256>>>(im_q, im_k);
    k_loss<<<NCLUST / 2, 1024>>>(out);
}